// round 1
// baseline (speedup 1.0000x reference)
#include <cuda_runtime.h>
#include <cuda_bf16.h>

#define ME   4096   // B*T rows
#define EMB  512
#define TT   2048
#define BB   2
#define HH   8
#define DD   64

// Scratch (no cudaMalloc allowed): 4 x 8 MB
__device__ float g_k[ME * EMB];
__device__ float g_q[ME * EMB];
__device__ float g_v[ME * EMB];
__device__ float g_o[ME * EMB];

// ---------------------------------------------------------------------------
// SGEMM: C[M,N] = A[M,K] * W[N,K]^T (+ bias). Both inputs row-major,
// K-contiguous. 128x128x8 tile, 256 threads, 8x8 microtile.
// ---------------------------------------------------------------------------
__global__ __launch_bounds__(256) void sgemm_nt(
    const float* __restrict__ A, const float* __restrict__ W,
    const float* __restrict__ bias, float* __restrict__ C,
    int M, int N, int K)
{
    __shared__ float As[8][132];
    __shared__ float Bs[8][132];

    const int tid = threadIdx.x;
    const int ty  = tid >> 4;        // 0..15
    const int tx  = tid & 15;        // 0..15
    const int lr  = tid >> 1;        // 0..127 (loader row)
    const int lh  = (tid & 1) * 4;   // 0 or 4  (loader k-offset)
    const int row0 = blockIdx.x * 128;
    const int col0 = blockIdx.y * 128;

    const float* Ag = A + (size_t)(row0 + lr) * K + lh;
    const float* Wg = W + (size_t)(col0 + lr) * K + lh;

    float acc[8][8];
#pragma unroll
    for (int i = 0; i < 8; i++)
#pragma unroll
        for (int j = 0; j < 8; j++) acc[i][j] = 0.f;

    for (int k0 = 0; k0 < K; k0 += 8) {
        float4 av = *(const float4*)(Ag + k0);
        float4 wv = *(const float4*)(Wg + k0);
        __syncthreads();
        As[lh + 0][lr] = av.x; As[lh + 1][lr] = av.y;
        As[lh + 2][lr] = av.z; As[lh + 3][lr] = av.w;
        Bs[lh + 0][lr] = wv.x; Bs[lh + 1][lr] = wv.y;
        Bs[lh + 2][lr] = wv.z; Bs[lh + 3][lr] = wv.w;
        __syncthreads();
#pragma unroll
        for (int kk = 0; kk < 8; kk++) {
            float a[8], b[8];
            *(float4*)&a[0] = *(const float4*)&As[kk][ty * 8];
            *(float4*)&a[4] = *(const float4*)&As[kk][ty * 8 + 4];
            *(float4*)&b[0] = *(const float4*)&Bs[kk][tx * 8];
            *(float4*)&b[4] = *(const float4*)&Bs[kk][tx * 8 + 4];
#pragma unroll
            for (int i = 0; i < 8; i++)
#pragma unroll
                for (int j = 0; j < 8; j++)
                    acc[i][j] += a[i] * b[j];
        }
    }

    float4 bv0 = make_float4(0.f, 0.f, 0.f, 0.f);
    float4 bv1 = make_float4(0.f, 0.f, 0.f, 0.f);
    if (bias) {
        bv0 = *(const float4*)&bias[col0 + tx * 8];
        bv1 = *(const float4*)&bias[col0 + tx * 8 + 4];
    }
#pragma unroll
    for (int i = 0; i < 8; i++) {
        const int row = row0 + ty * 8 + i;
        float* Cp = C + (size_t)row * N + col0 + tx * 8;
        float4 v0 = make_float4(acc[i][0] + bv0.x, acc[i][1] + bv0.y,
                                acc[i][2] + bv0.z, acc[i][3] + bv0.w);
        float4 v1 = make_float4(acc[i][4] + bv1.x, acc[i][5] + bv1.y,
                                acc[i][6] + bv1.z, acc[i][7] + bv1.w);
        *(float4*)&Cp[0] = v0;
        *(float4*)&Cp[4] = v1;
    }
}

// ---------------------------------------------------------------------------
// Per-head LayerNorm over D=64, then * EMB^-0.25. One warp per (token, head).
// ---------------------------------------------------------------------------
__global__ __launch_bounds__(256) void ln_head(
    float* __restrict__ buf, const float* __restrict__ gam,
    const float* __restrict__ bet)
{
    const int r    = blockIdx.x * 8 + (threadIdx.x >> 5);  // 0 .. ME*HH-1
    const int lane = threadIdx.x & 31;
    const int t = r >> 3;
    const int h = r & 7;
    float* p = buf + (size_t)t * EMB + h * DD;

    float e0 = p[lane], e1 = p[lane + 32];
    float s  = e0 + e1;
    float ss = e0 * e0 + e1 * e1;
#pragma unroll
    for (int off = 16; off; off >>= 1) {
        s  += __shfl_xor_sync(0xffffffffu, s, off);
        ss += __shfl_xor_sync(0xffffffffu, ss, off);
    }
    const float mean = s * (1.f / 64.f);
    const float var  = ss * (1.f / 64.f) - mean * mean;
    const float rs   = rsqrtf(var + 1e-5f);
    const float SC   = 0.21022410381342865f;  // 512^-0.25
    p[lane]      = ((e0 - mean) * rs * gam[lane]      + bet[lane])      * SC;
    p[lane + 32] = ((e1 - mean) * rs * gam[lane + 32] + bet[lane + 32]) * SC;
}

// ---------------------------------------------------------------------------
// Flash-attention (fp32 SIMT). Block = 64 queries for one (b,h).
// S-tile and O-tile as 64x64x64 register GEMMs, online softmax.
// smem: Qt[64][68] (D-major), KtP[64][68] (K^T, then reused for P),
//       Vs[64][64], mask tiles. 51712 B dynamic.
// ---------------------------------------------------------------------------
__global__ __launch_bounds__(256) void attn_kernel(const float* __restrict__ mask)
{
    extern __shared__ float sm[];
    float* Qt  = sm;                     // [64][68]
    float* KtP = sm + 64 * 68;           // [64][68]
    float* Vs  = sm + 2 * 64 * 68;       // [64][64]
    float* mk  = Vs + 64 * 64;           // [64]
    float* mq  = mk + 64;                // [64]

    const int b  = blockIdx.z;
    const int h  = blockIdx.y;
    const int t0 = blockIdx.x * 64;
    const int tid = threadIdx.x;
    const int ty = tid >> 4;   // 0..15 -> query rows ty*4..ty*4+3
    const int tx = tid & 15;   // 0..15 -> key cols / out dims tx*4..tx*4+3

    const size_t headoff = (size_t)b * TT * EMB + (size_t)h * DD;
    const float* qg = g_q + headoff;
    const float* kg = g_k + headoff;
    const float* vg = g_v + headoff;
    float*       og = g_o + headoff;

    // Load Q tile transposed (D-major)
    for (int idx = tid; idx < 64 * 64; idx += 256) {
        int r = idx >> 6, d = idx & 63;
        Qt[d * 68 + r] = qg[(size_t)(t0 + r) * EMB + d];
    }
    if (tid < 64) mq[tid] = mask[b * TT + t0 + tid];

    float o[4][4], m_i[4], l_i[4];
#pragma unroll
    for (int i = 0; i < 4; i++) {
        m_i[i] = -1e30f; l_i[i] = 0.f;
#pragma unroll
        for (int j = 0; j < 4; j++) o[i][j] = 0.f;
    }

    for (int s0 = 0; s0 < TT; s0 += 64) {
        __syncthreads();  // prior PV reads done / Qt,mq visible on first iter
        for (int idx = tid; idx < 64 * 64; idx += 256) {
            int r = idx >> 6, d = idx & 63;
            KtP[d * 68 + r] = kg[(size_t)(s0 + r) * EMB + d];
            Vs[idx]         = vg[(size_t)(s0 + r) * EMB + d];
        }
        if (tid < 64) mk[tid] = mask[b * TT + s0 + tid];
        __syncthreads();

        // S = Q * K^T  (4x4 microtile per thread)
        float s[4][4];
#pragma unroll
        for (int i = 0; i < 4; i++)
#pragma unroll
            for (int j = 0; j < 4; j++) s[i][j] = 0.f;
#pragma unroll 8
        for (int kk = 0; kk < 64; kk++) {
            float a[4], bb[4];
            *(float4*)a  = *(const float4*)&Qt[kk * 68 + ty * 4];
            *(float4*)bb = *(const float4*)&KtP[kk * 68 + tx * 4];
#pragma unroll
            for (int i = 0; i < 4; i++)
#pragma unroll
                for (int j = 0; j < 4; j++)
                    s[i][j] += a[i] * bb[j];
        }

        // mask + online softmax (register/shuffle only)
        float mkv[4], mqv[4];
#pragma unroll
        for (int j = 0; j < 4; j++) mkv[j] = mk[tx * 4 + j];
#pragma unroll
        for (int i = 0; i < 4; i++) mqv[i] = mq[ty * 4 + i];

#pragma unroll
        for (int i = 0; i < 4; i++) {
            float mx = -1e30f;
#pragma unroll
            for (int j = 0; j < 4; j++) {
                bool ok = (mqv[i] > 0.f) && (mkv[j] > 0.f);
                s[i][j] = ok ? s[i][j] : -1e30f;
                mx = fmaxf(mx, s[i][j]);
            }
#pragma unroll
            for (int off = 8; off; off >>= 1)
                mx = fmaxf(mx, __shfl_xor_sync(0xffffffffu, mx, off));
            const float mnew = fmaxf(m_i[i], mx);
            const float c = __expf(m_i[i] - mnew);
            float rsum = 0.f;
#pragma unroll
            for (int j = 0; j < 4; j++) {
                float pv = __expf(s[i][j] - mnew);
                s[i][j] = pv;
                rsum += pv;
            }
#pragma unroll
            for (int off = 8; off; off >>= 1)
                rsum += __shfl_xor_sync(0xffffffffu, rsum, off);
            l_i[i] = l_i[i] * c + rsum;
            m_i[i] = mnew;
#pragma unroll
            for (int j = 0; j < 4; j++) o[i][j] *= c;
        }

        __syncthreads();  // all threads done reading KtP as K
#pragma unroll
        for (int i = 0; i < 4; i++)
            *(float4*)&KtP[(ty * 4 + i) * 68 + tx * 4] =
                make_float4(s[i][0], s[i][1], s[i][2], s[i][3]);
        __syncthreads();  // P visible

        // O += P * V
#pragma unroll 8
        for (int kk = 0; kk < 64; kk++) {
            float bb[4];
            *(float4*)bb = *(const float4*)&Vs[kk * 64 + tx * 4];
#pragma unroll
            for (int i = 0; i < 4; i++) {
                float pa = KtP[(ty * 4 + i) * 68 + kk];
#pragma unroll
                for (int j = 0; j < 4; j++)
                    o[i][j] += pa * bb[j];
            }
        }
    }

    // epilogue: O / l
#pragma unroll
    for (int i = 0; i < 4; i++) {
        const float inv = 1.f / l_i[i];
        const int trow = t0 + ty * 4 + i;
        *(float4*)&og[(size_t)trow * EMB + tx * 4] =
            make_float4(o[i][0] * inv, o[i][1] * inv,
                        o[i][2] * inv, o[i][3] * inv);
    }
}

// ---------------------------------------------------------------------------
extern "C" void kernel_launch(void* const* d_in, const int* in_sizes, int n_in,
                              void* d_out, int out_size)
{
    const float* x    = (const float*)d_in[0];
    const float* mask = (const float*)d_in[1];
    const float* Wk   = (const float*)d_in[2];
    const float* Wq   = (const float*)d_in[3];
    const float* Wv   = (const float*)d_in[4];
    const float* Wu   = (const float*)d_in[5];
    const float* bu   = (const float*)d_in[6];
    const float* klng = (const float*)d_in[7];
    const float* klnb = (const float*)d_in[8];
    const float* qlng = (const float*)d_in[9];
    const float* qlnb = (const float*)d_in[10];
    float* out = (float*)d_out;

    float *gk, *gq, *gv, *go;
    cudaGetSymbolAddress((void**)&gk, g_k);
    cudaGetSymbolAddress((void**)&gq, g_q);
    cudaGetSymbolAddress((void**)&gv, g_v);
    cudaGetSymbolAddress((void**)&go, g_o);

    dim3 ggrid(ME / 128, EMB / 128);
    sgemm_nt<<<ggrid, 256>>>(x, Wk, nullptr, gk, ME, EMB, EMB);
    sgemm_nt<<<ggrid, 256>>>(x, Wq, nullptr, gq, ME, EMB, EMB);
    sgemm_nt<<<ggrid, 256>>>(x, Wv, nullptr, gv, ME, EMB, EMB);

    ln_head<<<ME * HH / 8, 256>>>(gk, klng, klnb);
    ln_head<<<ME * HH / 8, 256>>>(gq, qlng, qlnb);

    const int SMEM = (2 * 64 * 68 + 64 * 64 + 128) * (int)sizeof(float);  // 51712
    cudaFuncSetAttribute(attn_kernel,
                         cudaFuncAttributeMaxDynamicSharedMemorySize, SMEM);
    attn_kernel<<<dim3(TT / 64, HH, BB), 256, SMEM>>>(mask);

    sgemm_nt<<<ggrid, 256>>>(go, Wu, bu, out, ME, EMB, EMB);
}

// round 2
// speedup vs baseline: 1.0612x; 1.0612x over previous
#include <cuda_runtime.h>
#include <cuda_bf16.h>

#define ME   4096   // B*T rows
#define EMB  512
#define TT   2048
#define BB   2
#define HH   8
#define DD   64

typedef unsigned long long u64;

// Scratch (no cudaMalloc allowed): 4 x 8 MB
__device__ float g_k[ME * EMB];
__device__ float g_q[ME * EMB];
__device__ float g_v[ME * EMB];
__device__ float g_o[ME * EMB];

// ---- packed fp32x2 helpers (Blackwell FFMA2 path) --------------------------
__device__ __forceinline__ u64 pack2(float x, float y) {
    u64 r;
    asm("mov.b64 %0, {%1, %2};" : "=l"(r) : "f"(x), "f"(y));
    return r;
}
__device__ __forceinline__ void ffma2(u64& d, u64 a, u64 b) {
    asm("fma.rn.f32x2 %0, %1, %2, %0;" : "+l"(d) : "l"(a), "l"(b));
}
__device__ __forceinline__ u64 mul2(u64 a, u64 b) {
    u64 r;
    asm("mul.rn.f32x2 %0, %1, %2;" : "=l"(r) : "l"(a), "l"(b));
    return r;
}
__device__ __forceinline__ float2 unpack2(u64 v) {
    float2 f;
    asm("mov.b64 {%0, %1}, %2;" : "=f"(f.x), "=f"(f.y) : "l"(v));
    return f;
}

// ---------------------------------------------------------------------------
// SGEMM: C[M,N] = A[M,K] * W[N,K]^T (+ bias). 128x128x8 tile, 256 threads,
// 8x8 microtile computed as 8x4 packed-f32x2 accumulators.
// ---------------------------------------------------------------------------
__global__ __launch_bounds__(256) void sgemm_nt(
    const float* __restrict__ A, const float* __restrict__ W,
    const float* __restrict__ bias, float* __restrict__ C,
    int M, int N, int K)
{
    __shared__ float As[8][132];
    __shared__ float Bs[8][132];

    const int tid = threadIdx.x;
    const int ty  = tid >> 4;        // 0..15
    const int tx  = tid & 15;        // 0..15
    const int lr  = tid >> 1;        // 0..127 (loader row)
    const int lh  = (tid & 1) * 4;   // 0 or 4  (loader k-offset)
    const int row0 = blockIdx.x * 128;
    const int col0 = blockIdx.y * 128;

    const float* Ag = A + (size_t)(row0 + lr) * K + lh;
    const float* Wg = W + (size_t)(col0 + lr) * K + lh;

    u64 acc[8][4];
#pragma unroll
    for (int i = 0; i < 8; i++)
#pragma unroll
        for (int j = 0; j < 4; j++) acc[i][j] = 0ull;

    for (int k0 = 0; k0 < K; k0 += 8) {
        float4 av = *(const float4*)(Ag + k0);
        float4 wv = *(const float4*)(Wg + k0);
        __syncthreads();
        As[lh + 0][lr] = av.x; As[lh + 1][lr] = av.y;
        As[lh + 2][lr] = av.z; As[lh + 3][lr] = av.w;
        Bs[lh + 0][lr] = wv.x; Bs[lh + 1][lr] = wv.y;
        Bs[lh + 2][lr] = wv.z; Bs[lh + 3][lr] = wv.w;
        __syncthreads();
#pragma unroll
        for (int kk = 0; kk < 8; kk++) {
            float a[8];
            *(float4*)&a[0] = *(const float4*)&As[kk][ty * 8];
            *(float4*)&a[4] = *(const float4*)&As[kk][ty * 8 + 4];
            // b pairs: contiguous floats in smem -> 64-bit halves of LDS.128
            ulonglong2 b01 = *(const ulonglong2*)&Bs[kk][tx * 8];
            ulonglong2 b23 = *(const ulonglong2*)&Bs[kk][tx * 8 + 4];
            u64 a2[8];
#pragma unroll
            for (int i = 0; i < 8; i++) a2[i] = pack2(a[i], a[i]);
#pragma unroll
            for (int i = 0; i < 8; i++) {
                ffma2(acc[i][0], a2[i], b01.x);
                ffma2(acc[i][1], a2[i], b01.y);
                ffma2(acc[i][2], a2[i], b23.x);
                ffma2(acc[i][3], a2[i], b23.y);
            }
        }
    }

    float bv[8] = {0.f, 0.f, 0.f, 0.f, 0.f, 0.f, 0.f, 0.f};
    if (bias) {
        *(float4*)&bv[0] = *(const float4*)&bias[col0 + tx * 8];
        *(float4*)&bv[4] = *(const float4*)&bias[col0 + tx * 8 + 4];
    }
#pragma unroll
    for (int i = 0; i < 8; i++) {
        const int row = row0 + ty * 8 + i;
        float* Cp = C + (size_t)row * N + col0 + tx * 8;
        float2 c0 = unpack2(acc[i][0]);
        float2 c1 = unpack2(acc[i][1]);
        float2 c2 = unpack2(acc[i][2]);
        float2 c3 = unpack2(acc[i][3]);
        *(float4*)&Cp[0] = make_float4(c0.x + bv[0], c0.y + bv[1],
                                       c1.x + bv[2], c1.y + bv[3]);
        *(float4*)&Cp[4] = make_float4(c2.x + bv[4], c2.y + bv[5],
                                       c3.x + bv[6], c3.y + bv[7]);
    }
}

// ---------------------------------------------------------------------------
// Per-head LayerNorm over D=64, then * EMB^-0.25. One warp per (token, head).
// ---------------------------------------------------------------------------
__global__ __launch_bounds__(256) void ln_head(
    float* __restrict__ buf, const float* __restrict__ gam,
    const float* __restrict__ bet)
{
    const int r    = blockIdx.x * 8 + (threadIdx.x >> 5);  // 0 .. ME*HH-1
    const int lane = threadIdx.x & 31;
    const int t = r >> 3;
    const int h = r & 7;
    float* p = buf + (size_t)t * EMB + h * DD;

    float e0 = p[lane], e1 = p[lane + 32];
    float s  = e0 + e1;
    float ss = e0 * e0 + e1 * e1;
#pragma unroll
    for (int off = 16; off; off >>= 1) {
        s  += __shfl_xor_sync(0xffffffffu, s, off);
        ss += __shfl_xor_sync(0xffffffffu, ss, off);
    }
    const float mean = s * (1.f / 64.f);
    const float var  = ss * (1.f / 64.f) - mean * mean;
    const float rs   = rsqrtf(var + 1e-5f);
    const float SC   = 0.21022410381342865f;  // 512^-0.25
    p[lane]      = ((e0 - mean) * rs * gam[lane]      + bet[lane])      * SC;
    p[lane + 32] = ((e1 - mean) * rs * gam[lane + 32] + bet[lane + 32]) * SC;
}

// ---------------------------------------------------------------------------
// Flash-attention (fp32x2 SIMT). Block = 64 queries for one (b,h).
// ---------------------------------------------------------------------------
__global__ __launch_bounds__(256) void attn_kernel(const float* __restrict__ mask)
{
    extern __shared__ float sm[];
    float* Qt  = sm;                     // [64][68]
    float* KtP = sm + 64 * 68;           // [64][68]
    float* Vs  = sm + 2 * 64 * 68;       // [64][64]
    float* mk  = Vs + 64 * 64;           // [64]
    float* mq  = mk + 64;                // [64]

    const int b  = blockIdx.z;
    const int h  = blockIdx.y;
    const int t0 = blockIdx.x * 64;
    const int tid = threadIdx.x;
    const int ty = tid >> 4;   // 0..15 -> query rows ty*4..ty*4+3
    const int tx = tid & 15;   // 0..15 -> key cols / out dims tx*4..tx*4+3

    const size_t headoff = (size_t)b * TT * EMB + (size_t)h * DD;
    const float* qg = g_q + headoff;
    const float* kg = g_k + headoff;
    const float* vg = g_v + headoff;
    float*       og = g_o + headoff;

    // Load Q tile transposed (D-major)
    for (int idx = tid; idx < 64 * 64; idx += 256) {
        int r = idx >> 6, d = idx & 63;
        Qt[d * 68 + r] = qg[(size_t)(t0 + r) * EMB + d];
    }
    if (tid < 64) mq[tid] = mask[b * TT + t0 + tid];

    u64 o2[4][2];
    float m_i[4], l_i[4];
#pragma unroll
    for (int i = 0; i < 4; i++) {
        m_i[i] = -1e30f; l_i[i] = 0.f;
        o2[i][0] = 0ull; o2[i][1] = 0ull;
    }

    for (int s0 = 0; s0 < TT; s0 += 64) {
        __syncthreads();  // prior PV reads done / Qt,mq visible on first iter
        for (int idx = tid; idx < 64 * 64; idx += 256) {
            int r = idx >> 6, d = idx & 63;
            KtP[d * 68 + r] = kg[(size_t)(s0 + r) * EMB + d];
            Vs[idx]         = vg[(size_t)(s0 + r) * EMB + d];
        }
        if (tid < 64) mk[tid] = mask[b * TT + s0 + tid];
        __syncthreads();

        // S = Q * K^T  (packed f32x2: 4x2 accumulators)
        u64 s2[4][2];
#pragma unroll
        for (int i = 0; i < 4; i++) { s2[i][0] = 0ull; s2[i][1] = 0ull; }
#pragma unroll 8
        for (int kk = 0; kk < 64; kk++) {
            float a[4];
            *(float4*)a = *(const float4*)&Qt[kk * 68 + ty * 4];
            ulonglong2 bb = *(const ulonglong2*)&KtP[kk * 68 + tx * 4];
            u64 a2[4];
#pragma unroll
            for (int i = 0; i < 4; i++) a2[i] = pack2(a[i], a[i]);
#pragma unroll
            for (int i = 0; i < 4; i++) {
                ffma2(s2[i][0], a2[i], bb.x);
                ffma2(s2[i][1], a2[i], bb.y);
            }
        }

        // unpack scores
        float s[4][4];
#pragma unroll
        for (int i = 0; i < 4; i++) {
            float2 p0 = unpack2(s2[i][0]);
            float2 p1 = unpack2(s2[i][1]);
            s[i][0] = p0.x; s[i][1] = p0.y; s[i][2] = p1.x; s[i][3] = p1.y;
        }

        // mask + online softmax (register/shuffle only)
        float mkv[4], mqv[4];
#pragma unroll
        for (int j = 0; j < 4; j++) mkv[j] = mk[tx * 4 + j];
#pragma unroll
        for (int i = 0; i < 4; i++) mqv[i] = mq[ty * 4 + i];

#pragma unroll
        for (int i = 0; i < 4; i++) {
            float mx = -1e30f;
#pragma unroll
            for (int j = 0; j < 4; j++) {
                bool ok = (mqv[i] > 0.f) && (mkv[j] > 0.f);
                s[i][j] = ok ? s[i][j] : -1e30f;
                mx = fmaxf(mx, s[i][j]);
            }
#pragma unroll
            for (int off = 8; off; off >>= 1)
                mx = fmaxf(mx, __shfl_xor_sync(0xffffffffu, mx, off));
            const float mnew = fmaxf(m_i[i], mx);
            const float c = __expf(m_i[i] - mnew);
            float rsum = 0.f;
#pragma unroll
            for (int j = 0; j < 4; j++) {
                float pv = __expf(s[i][j] - mnew);
                s[i][j] = pv;
                rsum += pv;
            }
#pragma unroll
            for (int off = 8; off; off >>= 1)
                rsum += __shfl_xor_sync(0xffffffffu, rsum, off);
            l_i[i] = l_i[i] * c + rsum;
            m_i[i] = mnew;
            u64 c2 = pack2(c, c);
            o2[i][0] = mul2(o2[i][0], c2);
            o2[i][1] = mul2(o2[i][1], c2);
        }

        __syncthreads();  // all threads done reading KtP as K
#pragma unroll
        for (int i = 0; i < 4; i++)
            *(float4*)&KtP[(ty * 4 + i) * 68 + tx * 4] =
                make_float4(s[i][0], s[i][1], s[i][2], s[i][3]);
        __syncthreads();  // P visible

        // O += P * V  (packed f32x2)
#pragma unroll 8
        for (int kk = 0; kk < 64; kk++) {
            ulonglong2 bb = *(const ulonglong2*)&Vs[kk * 64 + tx * 4];
#pragma unroll
            for (int i = 0; i < 4; i++) {
                float pa = KtP[(ty * 4 + i) * 68 + kk];
                u64 pa2 = pack2(pa, pa);
                ffma2(o2[i][0], pa2, bb.x);
                ffma2(o2[i][1], pa2, bb.y);
            }
        }
    }

    // epilogue: O / l
#pragma unroll
    for (int i = 0; i < 4; i++) {
        const float inv = 1.f / l_i[i];
        const int trow = t0 + ty * 4 + i;
        float2 p0 = unpack2(o2[i][0]);
        float2 p1 = unpack2(o2[i][1]);
        *(float4*)&og[(size_t)trow * EMB + tx * 4] =
            make_float4(p0.x * inv, p0.y * inv, p1.x * inv, p1.y * inv);
    }
}

// ---------------------------------------------------------------------------
extern "C" void kernel_launch(void* const* d_in, const int* in_sizes, int n_in,
                              void* d_out, int out_size)
{
    const float* x    = (const float*)d_in[0];
    const float* mask = (const float*)d_in[1];
    const float* Wk   = (const float*)d_in[2];
    const float* Wq   = (const float*)d_in[3];
    const float* Wv   = (const float*)d_in[4];
    const float* Wu   = (const float*)d_in[5];
    const float* bu   = (const float*)d_in[6];
    const float* klng = (const float*)d_in[7];
    const float* klnb = (const float*)d_in[8];
    const float* qlng = (const float*)d_in[9];
    const float* qlnb = (const float*)d_in[10];
    float* out = (float*)d_out;

    float *gk, *gq, *gv, *go;
    cudaGetSymbolAddress((void**)&gk, g_k);
    cudaGetSymbolAddress((void**)&gq, g_q);
    cudaGetSymbolAddress((void**)&gv, g_v);
    cudaGetSymbolAddress((void**)&go, g_o);

    dim3 ggrid(ME / 128, EMB / 128);
    sgemm_nt<<<ggrid, 256>>>(x, Wk, nullptr, gk, ME, EMB, EMB);
    sgemm_nt<<<ggrid, 256>>>(x, Wq, nullptr, gq, ME, EMB, EMB);
    sgemm_nt<<<ggrid, 256>>>(x, Wv, nullptr, gv, ME, EMB, EMB);

    ln_head<<<ME * HH / 8, 256>>>(gk, klng, klnb);
    ln_head<<<ME * HH / 8, 256>>>(gq, qlng, qlnb);

    const int SMEM = (2 * 64 * 68 + 64 * 64 + 128) * (int)sizeof(float);  // 51712
    cudaFuncSetAttribute(attn_kernel,
                         cudaFuncAttributeMaxDynamicSharedMemorySize, SMEM);
    attn_kernel<<<dim3(TT / 64, HH, BB), 256, SMEM>>>(mask);

    sgemm_nt<<<ggrid, 256>>>(go, Wu, bu, out, ME, EMB, EMB);
}

// round 3
// speedup vs baseline: 2.4372x; 2.2966x over previous
#include <cuda_runtime.h>
#include <cuda_bf16.h>

#define ME   4096   // B*T rows
#define EMB  512
#define TT   2048
#define BB   2
#define HH   8
#define DD   64

typedef __nv_bfloat16 bf16;

// ---- scratch (device globals; no cudaMalloc allowed) -----------------------
__device__ float g_q[ME * EMB];
__device__ float g_k[ME * EMB];
__device__ __align__(16) bf16 g_xh[ME * EMB];
__device__ __align__(16) bf16 g_xl[ME * EMB];
__device__ __align__(16) bf16 g_qh[ME * EMB];
__device__ __align__(16) bf16 g_ql[ME * EMB];
__device__ __align__(16) bf16 g_kh[ME * EMB];
__device__ __align__(16) bf16 g_kl[ME * EMB];
__device__ __align__(16) bf16 g_vh[ME * EMB];
__device__ __align__(16) bf16 g_vl[ME * EMB];
__device__ __align__(16) bf16 g_oh[ME * EMB];
__device__ __align__(16) bf16 g_ol[ME * EMB];
__device__ __align__(16) bf16 g_wh[4 * EMB * EMB];
__device__ __align__(16) bf16 g_wl[4 * EMB * EMB];

// ---- helpers ----------------------------------------------------------------
__device__ __forceinline__ unsigned sa(const void* p) {
    return (unsigned)__cvta_generic_to_shared(p);
}
__device__ __forceinline__ void ldsm4(unsigned r[4], unsigned addr) {
    asm volatile("ldmatrix.sync.aligned.m8n8.x4.shared.b16 {%0,%1,%2,%3}, [%4];"
                 : "=r"(r[0]), "=r"(r[1]), "=r"(r[2]), "=r"(r[3]) : "r"(addr));
}
__device__ __forceinline__ void ldsm4t(unsigned r[4], unsigned addr) {
    asm volatile("ldmatrix.sync.aligned.m8n8.x4.trans.shared.b16 {%0,%1,%2,%3}, [%4];"
                 : "=r"(r[0]), "=r"(r[1]), "=r"(r[2]), "=r"(r[3]) : "r"(addr));
}
__device__ __forceinline__ void mma16816(float d[4], const unsigned a[4],
                                         unsigned b0, unsigned b1) {
    asm volatile(
        "mma.sync.aligned.m16n8k16.row.col.f32.bf16.bf16.f32 "
        "{%0,%1,%2,%3}, {%4,%5,%6,%7}, {%8,%9}, {%0,%1,%2,%3};"
        : "+f"(d[0]), "+f"(d[1]), "+f"(d[2]), "+f"(d[3])
        : "r"(a[0]), "r"(a[1]), "r"(a[2]), "r"(a[3]), "r"(b0), "r"(b1));
}
// pack two fp32 -> bf16x2 (lo in low half)
__device__ __forceinline__ unsigned pk2(float lo, float hi) {
    unsigned r;
    asm("cvt.rn.bf16x2.f32 %0, %1, %2;" : "=r"(r) : "f"(hi), "f"(lo));
    return r;
}
__device__ __forceinline__ void unpk2(unsigned u, float& lo, float& hi) {
    __nv_bfloat162 t = *reinterpret_cast<__nv_bfloat162*>(&u);
    lo = __bfloat162float(t.x);
    hi = __bfloat162float(t.y);
}

// ---- split fp32 -> (hi, lo) bf16 ---------------------------------------------
__global__ void split_f32(const float* __restrict__ in, bf16* __restrict__ h,
                          bf16* __restrict__ l, int n)
{
    int i = (blockIdx.x * blockDim.x + threadIdx.x) * 4;
    if (i >= n) return;
    float4 v = *(const float4*)&in[i];
    bf16 h0 = __float2bfloat16_rn(v.x), h1 = __float2bfloat16_rn(v.y);
    bf16 h2 = __float2bfloat16_rn(v.z), h3 = __float2bfloat16_rn(v.w);
    __nv_bfloat162 hh0; hh0.x = h0; hh0.y = h1;
    __nv_bfloat162 hh1; hh1.x = h2; hh1.y = h3;
    *(__nv_bfloat162*)&h[i]     = hh0;
    *(__nv_bfloat162*)&h[i + 2] = hh1;
    __nv_bfloat162 ll0, ll1;
    ll0.x = __float2bfloat16_rn(v.x - __bfloat162float(h0));
    ll0.y = __float2bfloat16_rn(v.y - __bfloat162float(h1));
    ll1.x = __float2bfloat16_rn(v.z - __bfloat162float(h2));
    ll1.y = __float2bfloat16_rn(v.w - __bfloat162float(h3));
    *(__nv_bfloat162*)&l[i]     = ll0;
    *(__nv_bfloat162*)&l[i + 2] = ll1;
}

// ---- LayerNorm per head + scale, emits bf16 split -----------------------------
__global__ __launch_bounds__(256) void ln_head_split(
    const float* __restrict__ buf, const float* __restrict__ gam,
    const float* __restrict__ bet, bf16* __restrict__ oh, bf16* __restrict__ ol)
{
    const int r    = blockIdx.x * 8 + (threadIdx.x >> 5);  // 0 .. ME*HH-1
    const int lane = threadIdx.x & 31;
    const int t = r >> 3;
    const int h = r & 7;
    const size_t base = (size_t)t * EMB + h * DD;
    const float* p = buf + base;

    float e0 = p[lane], e1 = p[lane + 32];
    float s  = e0 + e1;
    float ss = e0 * e0 + e1 * e1;
#pragma unroll
    for (int off = 16; off; off >>= 1) {
        s  += __shfl_xor_sync(0xffffffffu, s, off);
        ss += __shfl_xor_sync(0xffffffffu, ss, off);
    }
    const float mean = s * (1.f / 64.f);
    const float var  = ss * (1.f / 64.f) - mean * mean;
    const float rs   = rsqrtf(var + 1e-5f);
    const float SC   = 0.21022410381342865f;  // 512^-0.25
    float v0 = ((e0 - mean) * rs * gam[lane]      + bet[lane])      * SC;
    float v1 = ((e1 - mean) * rs * gam[lane + 32] + bet[lane + 32]) * SC;
    bf16 h0 = __float2bfloat16_rn(v0);
    bf16 h1 = __float2bfloat16_rn(v1);
    oh[base + lane]      = h0;
    oh[base + lane + 32] = h1;
    ol[base + lane]      = __float2bfloat16_rn(v0 - __bfloat162float(h0));
    ol[base + lane + 32] = __float2bfloat16_rn(v1 - __bfloat162float(h1));
}

// ---- bf16-split GEMM: C[M,N] = (Ah+Al)[M,K] @ (Wh+Wl)[N,K]^T (+bias) ---------
// 3 terms: (Ah,Wh),(Ah,Wl),(Al,Wh). CTA tile 128x64, 8 warps (4 M x 2 N),
// warp tile 32x32 = 2 m-frags x 4 n-frags. Output: fp32 and/or bf16 split.
__global__ __launch_bounds__(256, 2) void proj_mma(
    const bf16* __restrict__ Ah, const bf16* __restrict__ Al,
    const bf16* __restrict__ Wh, const bf16* __restrict__ Wl,
    const float* __restrict__ bias, float* __restrict__ C,
    bf16* __restrict__ Ch, bf16* __restrict__ Cl, int M, int N, int K)
{
    __shared__ bf16 As[128 * 72];
    __shared__ bf16 Ws[64 * 72];

    const int tid  = threadIdx.x;
    const int lane = tid & 31;
    const int w    = tid >> 5;
    const int wr   = w & 3;       // warp row (32 rows each)
    const int wc   = w >> 2;      // warp col (32 cols each)
    const int row0 = blockIdx.x * 128;
    const int col0 = blockIdx.y * 64;

    float acc[2][4][4];
#pragma unroll
    for (int m = 0; m < 2; m++)
#pragma unroll
        for (int j = 0; j < 4; j++)
#pragma unroll
            for (int e = 0; e < 4; e++) acc[m][j][e] = 0.f;

    const int lr = tid >> 3;         // 0..31
    const int lc = (tid & 7) * 8;    // col of uint4

    const unsigned a_addr = sa(&As[(wr * 32 + (lane & 15)) * 72 + (lane >> 4) * 8]);
    const unsigned b_addr = sa(&Ws[(wc * 32 + ((lane >> 4) << 3) + (lane & 7)) * 72 +
                                   (((lane >> 3) & 1) * 8)]);

    for (int term = 0; term < 3; term++) {
        const bf16* Ag = (term < 2) ? Ah : Al;
        const bf16* Wg = (term == 1) ? Wl : Wh;
        for (int k0 = 0; k0 < K; k0 += 64) {
            __syncthreads();
#pragma unroll
            for (int i = 0; i < 4; i++) {
                int r = lr + i * 32;
                *(uint4*)&As[r * 72 + lc] =
                    *(const uint4*)&Ag[(size_t)(row0 + r) * K + k0 + lc];
            }
#pragma unroll
            for (int i = 0; i < 2; i++) {
                int r = lr + i * 32;
                *(uint4*)&Ws[r * 72 + lc] =
                    *(const uint4*)&Wg[(size_t)(col0 + r) * K + k0 + lc];
            }
            __syncthreads();
#pragma unroll
            for (int kk = 0; kk < 4; kk++) {
                unsigned a0[4], a1[4];
                ldsm4(a0, a_addr + kk * 32);              // rows wr*32..+15
                ldsm4(a1, a_addr + kk * 32 + 16 * 144);   // rows +16
#pragma unroll
                for (int jp = 0; jp < 2; jp++) {
                    unsigned bb[4];
                    ldsm4(bb, b_addr + kk * 32 + jp * 16 * 144);
                    mma16816(acc[0][2 * jp],     a0, bb[0], bb[1]);
                    mma16816(acc[0][2 * jp + 1], a0, bb[2], bb[3]);
                    mma16816(acc[1][2 * jp],     a1, bb[0], bb[1]);
                    mma16816(acc[1][2 * jp + 1], a1, bb[2], bb[3]);
                }
            }
        }
    }

    // epilogue
#pragma unroll
    for (int m = 0; m < 2; m++) {
#pragma unroll
        for (int j = 0; j < 4; j++) {
            const int gr = row0 + wr * 32 + m * 16 + (lane >> 2);
            const int gc = col0 + wc * 32 + j * 8 + (lane & 3) * 2;
            float b0 = 0.f, b1 = 0.f;
            if (bias) { b0 = bias[gc]; b1 = bias[gc + 1]; }
            float v00 = acc[m][j][0] + b0, v01 = acc[m][j][1] + b1;
            float v10 = acc[m][j][2] + b0, v11 = acc[m][j][3] + b1;
            if (C) {
                *(float2*)&C[(size_t)gr * N + gc]       = make_float2(v00, v01);
                *(float2*)&C[(size_t)(gr + 8) * N + gc] = make_float2(v10, v11);
            }
            if (Ch) {
                unsigned h0 = pk2(v00, v01);
                unsigned h1 = pk2(v10, v11);
                *(unsigned*)&Ch[(size_t)gr * N + gc]       = h0;
                *(unsigned*)&Ch[(size_t)(gr + 8) * N + gc] = h1;
                float a_, b_;
                unpk2(h0, a_, b_);
                *(unsigned*)&Cl[(size_t)gr * N + gc] = pk2(v00 - a_, v01 - b_);
                unpk2(h1, a_, b_);
                *(unsigned*)&Cl[(size_t)(gr + 8) * N + gc] = pk2(v10 - a_, v11 - b_);
            }
        }
    }
}

// ---- flash attention on mma.sync bf16 (split) ---------------------------------
// Block: 128 thr = 4 warps, 64 queries (16/warp), key tiles of 64.
__global__ __launch_bounds__(128, 3) void attn_mma(const float* __restrict__ mask)
{
    extern __shared__ char smraw[];
    bf16* Qh_s = (bf16*)smraw;                 // [64][72]
    bf16* Ql_s = Qh_s + 64 * 72;
    bf16* Kh_s = Ql_s + 64 * 72;
    bf16* Kl_s = Kh_s + 64 * 72;
    bf16* Vh_s = Kl_s + 64 * 72;
    bf16* Vl_s = Vh_s + 64 * 72;
    float* mq  = (float*)(Vl_s + 64 * 72);
    float* mk  = mq + 64;

    const int b   = blockIdx.z;
    const int h   = blockIdx.y;
    const int t0  = blockIdx.x * 64;
    const int tid = threadIdx.x;
    const int lane = tid & 31;
    const int w    = tid >> 5;        // warp: rows w*16..w*16+15

    const int lr = tid >> 3;          // 0..15
    const int lc = (tid & 7) * 8;

    // load Q tiles (t0 rows) as bf16 hi/lo
#pragma unroll
    for (int i = 0; i < 4; i++) {
        int r = lr + i * 16;
        size_t gi = (size_t)(b * TT + t0 + r) * EMB + h * DD + lc;
        *(uint4*)&Qh_s[r * 72 + lc] = *(const uint4*)&g_qh[gi];
        *(uint4*)&Ql_s[r * 72 + lc] = *(const uint4*)&g_ql[gi];
    }
    if (tid < 64) mq[tid] = mask[b * TT + t0 + tid];

    // fragment addresses
    const unsigned qh_a = sa(&Qh_s[(w * 16 + (lane & 15)) * 72 + (lane >> 4) * 8]);
    const unsigned ql_a = sa(&Ql_s[(w * 16 + (lane & 15)) * 72 + (lane >> 4) * 8]);
    const int krow = ((lane >> 4) << 3) + (lane & 7);   // within 16-row pair block
    const unsigned kh_a = sa(&Kh_s[krow * 72 + ((lane >> 3) & 1) * 8]);
    const unsigned kl_a = sa(&Kl_s[krow * 72 + ((lane >> 3) & 1) * 8]);
    const int vrow = ((lane >> 3) & 1) * 8 + (lane & 7);
    const int vcol = ((lane >> 4) << 3);
    const unsigned vh_a = sa(&Vh_s[vrow * 72 + vcol]);
    const unsigned vl_a = sa(&Vl_s[vrow * 72 + vcol]);

    float oa[8][4];
#pragma unroll
    for (int j = 0; j < 8; j++)
#pragma unroll
        for (int e = 0; e < 4; e++) oa[j][e] = 0.f;
    float m_i[2] = {-1e30f, -1e30f};
    float l_i[2] = {0.f, 0.f};

    const float mq0 = (tid, mask[b * TT + t0 + w * 16 + (lane >> 2)]);
    const float mq1 = mask[b * TT + t0 + w * 16 + (lane >> 2) + 8];

    for (int s0 = 0; s0 < TT; s0 += 64) {
        __syncthreads();
#pragma unroll
        for (int i = 0; i < 4; i++) {
            int r = lr + i * 16;
            size_t gi = (size_t)(b * TT + s0 + r) * EMB + h * DD + lc;
            *(uint4*)&Kh_s[r * 72 + lc] = *(const uint4*)&g_kh[gi];
            *(uint4*)&Kl_s[r * 72 + lc] = *(const uint4*)&g_kl[gi];
            *(uint4*)&Vh_s[r * 72 + lc] = *(const uint4*)&g_vh[gi];
            *(uint4*)&Vl_s[r * 72 + lc] = *(const uint4*)&g_vl[gi];
        }
        if (tid < 64) mk[tid] = mask[b * TT + s0 + tid];
        __syncthreads();

        // ---- S = Q K^T (3 split terms) ----
        float sc[8][4];
#pragma unroll
        for (int j = 0; j < 8; j++)
#pragma unroll
            for (int e = 0; e < 4; e++) sc[j][e] = 0.f;

#pragma unroll
        for (int term = 0; term < 3; term++) {
            const unsigned qa = (term < 2) ? qh_a : ql_a;
            const unsigned ka = (term == 1) ? kl_a : kh_a;
#pragma unroll
            for (int kc = 0; kc < 4; kc++) {
                unsigned a[4];
                ldsm4(a, qa + kc * 32);
#pragma unroll
                for (int jp = 0; jp < 4; jp++) {
                    unsigned bb[4];
                    ldsm4(bb, ka + kc * 32 + jp * 16 * 144);
                    mma16816(sc[2 * jp],     a, bb[0], bb[1]);
                    mma16816(sc[2 * jp + 1], a, bb[2], bb[3]);
                }
            }
        }

        // ---- mask + online softmax ----
        float mx0 = -1e30f, mx1 = -1e30f;
#pragma unroll
        for (int j = 0; j < 8; j++) {
            int col = j * 8 + (lane & 3) * 2;
            float mk0 = mk[col], mk1 = mk[col + 1];
            sc[j][0] = (mq0 > 0.f && mk0 > 0.f) ? sc[j][0] : -1e30f;
            sc[j][1] = (mq0 > 0.f && mk1 > 0.f) ? sc[j][1] : -1e30f;
            sc[j][2] = (mq1 > 0.f && mk0 > 0.f) ? sc[j][2] : -1e30f;
            sc[j][3] = (mq1 > 0.f && mk1 > 0.f) ? sc[j][3] : -1e30f;
            mx0 = fmaxf(mx0, fmaxf(sc[j][0], sc[j][1]));
            mx1 = fmaxf(mx1, fmaxf(sc[j][2], sc[j][3]));
        }
        mx0 = fmaxf(mx0, __shfl_xor_sync(0xffffffffu, mx0, 1));
        mx0 = fmaxf(mx0, __shfl_xor_sync(0xffffffffu, mx0, 2));
        mx1 = fmaxf(mx1, __shfl_xor_sync(0xffffffffu, mx1, 1));
        mx1 = fmaxf(mx1, __shfl_xor_sync(0xffffffffu, mx1, 2));

        const float mn0 = fmaxf(m_i[0], mx0);
        const float mn1 = fmaxf(m_i[1], mx1);
        const float c0 = __expf(m_i[0] - mn0);
        const float c1 = __expf(m_i[1] - mn1);
        float rs0 = 0.f, rs1 = 0.f;
#pragma unroll
        for (int j = 0; j < 8; j++) {
            sc[j][0] = __expf(sc[j][0] - mn0);
            sc[j][1] = __expf(sc[j][1] - mn0);
            sc[j][2] = __expf(sc[j][2] - mn1);
            sc[j][3] = __expf(sc[j][3] - mn1);
            rs0 += sc[j][0] + sc[j][1];
            rs1 += sc[j][2] + sc[j][3];
        }
        rs0 += __shfl_xor_sync(0xffffffffu, rs0, 1);
        rs0 += __shfl_xor_sync(0xffffffffu, rs0, 2);
        rs1 += __shfl_xor_sync(0xffffffffu, rs1, 1);
        rs1 += __shfl_xor_sync(0xffffffffu, rs1, 2);
        l_i[0] = l_i[0] * c0 + rs0;
        l_i[1] = l_i[1] * c1 + rs1;
        m_i[0] = mn0; m_i[1] = mn1;
#pragma unroll
        for (int j = 0; j < 8; j++) {
            oa[j][0] *= c0; oa[j][1] *= c0;
            oa[j][2] *= c1; oa[j][3] *= c1;
        }

        // ---- pack P hi (bf16) in A-fragment form ----
        unsigned ph[8][2];
#pragma unroll
        for (int j = 0; j < 8; j++) {
            ph[j][0] = pk2(sc[j][0], sc[j][1]);
            ph[j][1] = pk2(sc[j][2], sc[j][3]);
        }

        // ---- O += P V (3 split terms) ----
#pragma unroll
        for (int term = 0; term < 3; term++) {
            const unsigned va = (term == 1) ? vl_a : vh_a;
#pragma unroll
            for (int kc = 0; kc < 4; kc++) {
                unsigned a[4];
                if (term < 2) {
                    a[0] = ph[2 * kc][0];     a[1] = ph[2 * kc][1];
                    a[2] = ph[2 * kc + 1][0]; a[3] = ph[2 * kc + 1][1];
                } else {
                    // residual P lo
                    float x, y;
                    unpk2(ph[2 * kc][0], x, y);
                    a[0] = pk2(sc[2 * kc][0] - x, sc[2 * kc][1] - y);
                    unpk2(ph[2 * kc][1], x, y);
                    a[1] = pk2(sc[2 * kc][2] - x, sc[2 * kc][3] - y);
                    unpk2(ph[2 * kc + 1][0], x, y);
                    a[2] = pk2(sc[2 * kc + 1][0] - x, sc[2 * kc + 1][1] - y);
                    unpk2(ph[2 * kc + 1][1], x, y);
                    a[3] = pk2(sc[2 * kc + 1][2] - x, sc[2 * kc + 1][3] - y);
                }
#pragma unroll
                for (int jp = 0; jp < 4; jp++) {
                    unsigned bb[4];
                    ldsm4t(bb, va + kc * 16 * 144 + jp * 32);
                    mma16816(oa[2 * jp],     a, bb[0], bb[1]);
                    mma16816(oa[2 * jp + 1], a, bb[2], bb[3]);
                }
            }
        }
    }

    // ---- epilogue: O / l -> bf16 split ----
    const float inv0 = 1.f / l_i[0];
    const float inv1 = 1.f / l_i[1];
    const int gr0 = b * TT + t0 + w * 16 + (lane >> 2);
#pragma unroll
    for (int j = 0; j < 8; j++) {
        const int col = h * DD + j * 8 + (lane & 3) * 2;
        float v00 = oa[j][0] * inv0, v01 = oa[j][1] * inv0;
        float v10 = oa[j][2] * inv1, v11 = oa[j][3] * inv1;
        unsigned h0 = pk2(v00, v01);
        unsigned h1 = pk2(v10, v11);
        *(unsigned*)&g_oh[(size_t)gr0 * EMB + col]       = h0;
        *(unsigned*)&g_oh[(size_t)(gr0 + 8) * EMB + col] = h1;
        float x, y;
        unpk2(h0, x, y);
        *(unsigned*)&g_ol[(size_t)gr0 * EMB + col] = pk2(v00 - x, v01 - y);
        unpk2(h1, x, y);
        *(unsigned*)&g_ol[(size_t)(gr0 + 8) * EMB + col] = pk2(v10 - x, v11 - y);
    }
}

// ---------------------------------------------------------------------------
extern "C" void kernel_launch(void* const* d_in, const int* in_sizes, int n_in,
                              void* d_out, int out_size)
{
    const float* x    = (const float*)d_in[0];
    const float* mask = (const float*)d_in[1];
    const float* Wk   = (const float*)d_in[2];
    const float* Wq   = (const float*)d_in[3];
    const float* Wv   = (const float*)d_in[4];
    const float* Wu   = (const float*)d_in[5];
    const float* bu   = (const float*)d_in[6];
    const float* klng = (const float*)d_in[7];
    const float* klnb = (const float*)d_in[8];
    const float* qlng = (const float*)d_in[9];
    const float* qlnb = (const float*)d_in[10];
    float* out = (float*)d_out;

    float *gq, *gk;
    bf16 *xh, *xl, *qh, *ql, *kh, *kl, *vh, *vl, *oh, *ol, *wh, *wl;
    cudaGetSymbolAddress((void**)&gq, g_q);
    cudaGetSymbolAddress((void**)&gk, g_k);
    cudaGetSymbolAddress((void**)&xh, g_xh);
    cudaGetSymbolAddress((void**)&xl, g_xl);
    cudaGetSymbolAddress((void**)&qh, g_qh);
    cudaGetSymbolAddress((void**)&ql, g_ql);
    cudaGetSymbolAddress((void**)&kh, g_kh);
    cudaGetSymbolAddress((void**)&kl, g_kl);
    cudaGetSymbolAddress((void**)&vh, g_vh);
    cudaGetSymbolAddress((void**)&vl, g_vl);
    cudaGetSymbolAddress((void**)&oh, g_oh);
    cudaGetSymbolAddress((void**)&ol, g_ol);
    cudaGetSymbolAddress((void**)&wh, g_wh);
    cudaGetSymbolAddress((void**)&wl, g_wl);

    const int WSZ = EMB * EMB;

    // splits
    split_f32<<<(ME * EMB / 4 + 255) / 256, 256>>>(x, xh, xl, ME * EMB);
    split_f32<<<(WSZ / 4 + 255) / 256, 256>>>(Wk, wh + 0 * WSZ, wl + 0 * WSZ, WSZ);
    split_f32<<<(WSZ / 4 + 255) / 256, 256>>>(Wq, wh + 1 * WSZ, wl + 1 * WSZ, WSZ);
    split_f32<<<(WSZ / 4 + 255) / 256, 256>>>(Wv, wh + 2 * WSZ, wl + 2 * WSZ, WSZ);
    split_f32<<<(WSZ / 4 + 255) / 256, 256>>>(Wu, wh + 3 * WSZ, wl + 3 * WSZ, WSZ);

    // projections
    dim3 pgrid(ME / 128, EMB / 64);
    proj_mma<<<pgrid, 256>>>(xh, xl, wh + 0 * WSZ, wl + 0 * WSZ, nullptr,
                             gk, nullptr, nullptr, ME, EMB, EMB);
    proj_mma<<<pgrid, 256>>>(xh, xl, wh + 1 * WSZ, wl + 1 * WSZ, nullptr,
                             gq, nullptr, nullptr, ME, EMB, EMB);
    proj_mma<<<pgrid, 256>>>(xh, xl, wh + 2 * WSZ, wl + 2 * WSZ, nullptr,
                             nullptr, vh, vl, ME, EMB, EMB);

    // per-head LN -> bf16 split
    ln_head_split<<<ME * HH / 8, 256>>>(gk, klng, klnb, kh, kl);
    ln_head_split<<<ME * HH / 8, 256>>>(gq, qlng, qlnb, qh, ql);

    // attention
    const int SMEM = 6 * 64 * 72 * (int)sizeof(bf16) + 2 * 64 * (int)sizeof(float);
    cudaFuncSetAttribute(attn_mma,
                         cudaFuncAttributeMaxDynamicSharedMemorySize, SMEM);
    attn_mma<<<dim3(TT / 64, HH, BB), 128, SMEM>>>(mask);

    // output projection
    proj_mma<<<pgrid, 256>>>(oh, ol, wh + 3 * WSZ, wl + 3 * WSZ, bu,
                             out, nullptr, nullptr, ME, EMB, EMB);
}